// round 17
// baseline (speedup 1.0000x reference)
#include <cuda_runtime.h>
#include <cuda_bf16.h>
#include <cuda_fp8.h>
#include <math.h>
#include <stdint.h>

// Problem constants
#define VOCAB   50000
#define N_SEQ   4096
#define N_DOCS  512
#define EMBD    300
#define HID     256
#define GATES   1024
#define T_COL   64
#define T_ROW   16

#define MCH     16          // sequences per chunk
#define NT      256         // 8 warps per CTA

#define NKT_H   8
#define NKT_X   10
#define XKW     84
#define XSB     336

#define SCL     16.0f
#define ISCL    0.00390625f // 1/256

// ---------------- device scratch ----------------
__device__ uint2  g_Whh2[2][NKT_H][64][32][2];
__device__ uint2  g_Wih[2][NKT_X][128][32];
__device__ float  g_bias[2][GATES];
__device__ uint32_t g_xprojF[2][VOCAB][512];   // 204.8 MB
__device__ float  g_acc[3][N_DOCS][HID];

__device__ __forceinline__ int perm_to_orig(int jp) {
    int p = jp >> 3, c = jp & 7;
    int gate = ((p & 1) << 1) | (c & 1);
    int unit = ((p >> 1) << 2) | (c >> 1);
    return gate * 256 + unit;
}

// ---------------- helpers ----------------
__device__ __forceinline__ float ftanh(float x) {
    float y; asm("tanh.approx.f32 %0, %1;" : "=f"(y) : "f"(x)); return y;
}
__device__ __forceinline__ float fsigm(float x) {
    return 0.5f * ftanh(0.5f * x) + 0.5f;
}
__device__ __forceinline__ uint32_t pack4_e4m3(float v0, float v1, float v2, float v3) {
    uint16_t lo, hi;
    asm("cvt.rn.satfinite.e4m3x2.f32 %0, %1, %2;" : "=h"(lo) : "f"(v1), "f"(v0));
    asm("cvt.rn.satfinite.e4m3x2.f32 %0, %1, %2;" : "=h"(hi) : "f"(v3), "f"(v2));
    return (uint32_t)lo | ((uint32_t)hi << 16);
}
__device__ __forceinline__ uint8_t f_to_e4m3(float v) {
    uint16_t r;
    asm("cvt.rn.satfinite.e4m3x2.f32 %0, %1, %2;" : "=h"(r) : "f"(0.f), "f"(v));
    return (uint8_t)r;
}
__device__ __forceinline__ uint32_t pack_bf16x2(float lo, float hi) {
    uint32_t r;
    asm("cvt.rn.bf16x2.f32 %0, %1, %2;" : "=r"(r) : "f"(hi), "f"(lo));
    return r;
}
__device__ __forceinline__ void mma16832(float* c, const uint32_t* a, uint32_t b0, uint32_t b1) {
    asm volatile(
        "mma.sync.aligned.m16n8k32.row.col.f32.e4m3.e4m3.f32 "
        "{%0,%1,%2,%3},{%4,%5,%6,%7},{%8,%9},{%0,%1,%2,%3};"
        : "+f"(c[0]), "+f"(c[1]), "+f"(c[2]), "+f"(c[3])
        : "r"(a[0]), "r"(a[1]), "r"(a[2]), "r"(a[3]), "r"(b0), "r"(b1));
}
__device__ __forceinline__ uint32_t smem_u32(const void* p) {
    uint32_t a;
    asm("{ .reg .u64 t; cvta.to.shared.u64 t, %1; cvt.u32.u64 %0, t; }" : "=r"(a) : "l"(p));
    return a;
}

// ---------------- prep ----------------
__global__ void prep_kernel(const float* cWih, const float* cWhh,
                            const float* cbih, const float* cbhh,
                            const float* rWih, const float* rWhh,
                            const float* rbih, const float* rbhh,
                            float* out) {
    int idx = blockIdx.x * blockDim.x + threadIdx.x;
    if (idx == 0) *out = 0.f;
    if (idx < 3 * N_DOCS * HID) (&g_acc[0][0][0])[idx] = 0.f;

    if (idx < 2 * GATES) {
        int bm = idx >> 10, jb = idx & 1023;
        int jbo = perm_to_orig(jb);
        const float* bih = bm ? rbih : cbih;
        const float* bhh = bm ? rbhh : cbhh;
        g_bias[bm][jb] = bih[jbo] + bhh[jbo];
    }

    int lane = idx & 31;
    int ntg  = (idx >> 5) & 127;
    int q    = idx >> 12;
    int tg = lane & 3, gg = lane >> 2;
    int jo = perm_to_orig(ntg * 8 + gg);

    if (idx < 2 * NKT_X * 128 * 32) {
        int kt  = q % NKT_X;
        int mat = q / NKT_X;
        const float* Wih = mat ? rWih : cWih;
        int k0 = kt * 32 + 4 * tg;
        float v[8];
        #pragma unroll
        for (int i = 0; i < 8; i++) {
            int k = k0 + (i >> 2) * 16 + (i & 3);
            v[i] = (k < EMBD) ? SCL * Wih[jo * EMBD + k] : 0.f;
        }
        uint2 w2;
        w2.x = pack4_e4m3(v[0], v[1], v[2], v[3]);
        w2.y = pack4_e4m3(v[4], v[5], v[6], v[7]);
        g_Wih[mat][kt][ntg][lane] = w2;
    }
    if (idx < 2 * NKT_H * 128 * 32) {
        int kt  = q % NKT_H;
        int mat = q / NKT_H;
        const float* Whh = mat ? rWhh : cWhh;
        int k0 = kt * 32 + 4 * tg;
        float v[8];
        #pragma unroll
        for (int i = 0; i < 8; i++) {
            int k = k0 + (i >> 2) * 16 + (i & 3);
            v[i] = SCL * Whh[jo * HID + k];
        }
        uint2 w2;
        w2.x = pack4_e4m3(v[0], v[1], v[2], v[3]);
        w2.y = pack4_e4m3(v[4], v[5], v[6], v[7]);
        g_Whh2[mat][kt][ntg >> 1][lane][ntg & 1] = w2;
    }
}

__global__ void dummy_kernel() {}

// ---------------- xproj ----------------
__global__ void __launch_bounds__(256, 2)
xproj_kernel(const float* emb) {
    __shared__ uint8_t As[32 * XSB];
    int bid = blockIdx.x;
    int mat = bid >= 1563;
    int vbase = (bid - mat * 1563) * 32;

    int tid = threadIdx.x;
    int w = tid >> 5, lane = tid & 31;
    int tg = lane & 3, gg = lane >> 2;

    for (int i = tid; i < 32 * XSB / 4; i += 256) ((uint32_t*)As)[i] = 0u;
    __syncthreads();

    {
        int m = tid >> 3, ts = tid & 7;
        int row = vbase + m; if (row >= VOCAB) row = 0;
        const float4* erow = (const float4*)(emb + (size_t)row * EMBD);
        uint32_t* arow = (uint32_t*)(As + m * XSB);
        for (int kk = ts; kk < EMBD / 4; kk += 8) {
            float4 v = __ldg(&erow[kk]);
            arow[kk] = pack4_e4m3(SCL * v.x, SCL * v.y, SCL * v.z, SCL * v.w);
        }
    }
    __syncthreads();

    const uint32_t* Aw = (const uint32_t*)As;
    const int a_base = gg * XKW + tg;

    #pragma unroll
    for (int h = 0; h < 2; h++) {
        int nt_base = (w << 4) + (h << 3);
        const uint2* Bp = &g_Wih[mat][0][0][0] + nt_base * 32 + lane;

        float acc[2][8][4];
        #pragma unroll
        for (int mt = 0; mt < 2; mt++)
            #pragma unroll
            for (int nt = 0; nt < 8; nt++)
                #pragma unroll
                for (int i = 0; i < 4; i++) acc[mt][nt][i] = 0.f;

        uint2 bb[8];
        #pragma unroll
        for (int nt = 0; nt < 8; nt++) bb[nt] = __ldg(Bp + nt * 32);
        #pragma unroll
        for (int kt = 0; kt < NKT_X; kt++) {
            uint2 bn[8];
            if (kt < NKT_X - 1) {
                const uint2* bk2 = Bp + (size_t)(kt + 1) * 128 * 32;
                #pragma unroll
                for (int nt = 0; nt < 8; nt++) bn[nt] = __ldg(bk2 + nt * 32);
            }
            uint32_t a[2][4];
            int ab = a_base + kt * 8;
            #pragma unroll
            for (int mt = 0; mt < 2; mt++) {
                int o = ab + mt * 16 * XKW;
                a[mt][0] = Aw[o];
                a[mt][1] = Aw[o + 8 * XKW];
                a[mt][2] = Aw[o + 4];
                a[mt][3] = Aw[o + 8 * XKW + 4];
            }
            #pragma unroll
            for (int nt = 0; nt < 8; nt++) {
                mma16832(acc[0][nt], a[0], bb[nt].x, bb[nt].y);
                mma16832(acc[1][nt], a[1], bb[nt].x, bb[nt].y);
            }
            #pragma unroll
            for (int nt = 0; nt < 8; nt++) bb[nt] = bn[nt];
        }

        #pragma unroll
        for (int nt = 0; nt < 8; nt++) {
            int tile = nt_base + nt;
            int jc = (tile << 3) + (tg << 1);
            int wp = ((tile >> 1) << 3) + (tg << 1) + (tile & 1);
            float b0 = g_bias[mat][jc], b1 = g_bias[mat][jc + 1];
            #pragma unroll
            for (int mt = 0; mt < 2; mt++) {
                int r0 = vbase + (mt << 4) + gg;
                int r1 = r0 + 8;
                if (r0 < VOCAB)
                    g_xprojF[mat][r0][wp] =
                        pack_bf16x2(acc[mt][nt][0] * ISCL + b0, acc[mt][nt][1] * ISCL + b1);
                if (r1 < VOCAB)
                    g_xprojF[mat][r1][wp] =
                        pack_bf16x2(acc[mt][nt][2] * ISCL + b0, acc[mt][nt][3] * ISCL + b1);
            }
        }
    }
}

// ---------------- main recurrent LSTM kernel: 2-CTA cluster split-N,
//                  DUAL-CHUNK interleave (latency hiding + L1-shared B) ----------------
__global__ void __cluster_dims__(2, 1, 1) __launch_bounds__(NT, 2)
lstm_kernel(const int* colT, const int* rowT, const int* negT,
            const int* clen, const int* rlen, const int* nlen,
            const int* cref, const int* rref, const int* nref) {
    __shared__ __align__(16) uint8_t  AsF0[2][NKT_H * 512];
    __shared__ __align__(16) uint8_t  AsF1[2][NKT_H * 512];
    __shared__ __nv_bfloat16  Hs[2][MCH * 264];
    __shared__ int            toksAll[2][MCH * T_COL];
    __shared__ int            lensS[2][MCH];
    __shared__ int            refS[2][MCH];
    __shared__ uint64_t       mbar[2];

    uint32_t rank;
    asm("mov.u32 %0, %%cluster_ctarank;" : "=r"(rank));

    // dual-chunk job map: cluster cid handles chunks [0]=A, [1]=B (same mat)
    int cid = blockIdx.x >> 1;                  // 0..383
    int mat, T;
    int taskC[2], chunkC[2];
    if (cid < 128) {                            // col pairs, LPT-ish over 74-stride
        int j = (cid < 74) ? cid : (201 - cid); // 0..73, then 127..74
        taskC[0] = 0; chunkC[0] = 2 * j;
        taskC[1] = 0; chunkC[1] = 2 * j + 1;
        mat = 0; T = T_COL;
    } else {                                    // row s + neg s
        int s = cid - 128;                      // 0..255
        taskC[0] = 1; chunkC[0] = s;
        taskC[1] = 2; chunkC[1] = s;
        mat = 1; T = T_ROW;
    }

    const int* toksP[2]; const int* lensP[2]; const int* refsP[2];
    #pragma unroll
    for (int ch = 0; ch < 2; ch++) {
        int task = taskC[ch];
        toksP[ch] = (task == 0) ? colT : (task == 1) ? rowT : negT;
        lensP[ch] = (task == 0) ? clen : (task == 1) ? rlen : nlen;
        refsP[ch] = (task == 0) ? cref : (task == 1) ? rref : nref;
    }

    int tid = threadIdx.x;
    int w = tid >> 5, lane = tid & 31;
    int tg = lane & 3, gg = lane >> 2;

    // init smem
    #pragma unroll
    for (int ch = 0; ch < 2; ch++) {
        int n0 = chunkC[ch] * MCH;
        for (int i = tid; i < NKT_H * 512 / 4; i += NT) ((uint32_t*)AsF0[ch])[i] = 0u;
        for (int i = tid; i < MCH * T; i += NT) toksAll[ch][i] = toksP[ch][n0 * T + i];
        if (tid < MCH) lensS[ch][tid] = lensP[ch][n0 + tid];
    }
    uint32_t mbarA0 = smem_u32(&mbar[0]);
    uint32_t mbarA1 = smem_u32(&mbar[1]);
    if (tid == 0) {
        asm volatile("mbarrier.init.shared.b64 [%0], %1;" :: "r"(mbarA0), "r"(2 * NT) : "memory");
        asm volatile("mbarrier.init.shared.b64 [%0], %1;" :: "r"(mbarA1), "r"(2 * NT) : "memory");
    }

    // peer addresses
    uint32_t peer = rank ^ 1u;
    uint32_t pAs0[2], pAs1[2], pMbar[2];
    #pragma unroll
    for (int ch = 0; ch < 2; ch++) {
        uint32_t a0 = smem_u32(AsF0[ch]), a1 = smem_u32(AsF1[ch]);
        asm("mapa.shared::cluster.u32 %0, %1, %2;" : "=r"(pAs0[ch]) : "r"(a0), "r"(peer));
        asm("mapa.shared::cluster.u32 %0, %1, %2;" : "=r"(pAs1[ch]) : "r"(a1), "r"(peer));
    }
    asm("mapa.shared::cluster.u32 %0, %1, %2;" : "=r"(pMbar[0]) : "r"(mbarA0), "r"(peer));
    asm("mapa.shared::cluster.u32 %0, %1, %2;" : "=r"(pMbar[1]) : "r"(mbarA1), "r"(peer));

    asm volatile("barrier.cluster.arrive.aligned;" ::: "memory");
    asm volatile("barrier.cluster.wait.aligned;" ::: "memory");

    int mlen[2];
    mlen[0] = lensS[0][0];
    mlen[1] = lensS[1][0];
    int maxT = max(mlen[0], mlen[1]);
    int len0C[2], len1C[2];
    #pragma unroll
    for (int ch = 0; ch < 2; ch++) { len0C[ch] = lensS[ch][gg]; len1C[ch] = lensS[ch][gg + 8]; }

    const uint32_t* xpF = &g_xprojF[mat][0][0];
    const uint4* Bq = (const uint4*)&g_Whh2[mat][0][0][0][0];
    int p0 = (int)rank * 32 + (w << 2);

    uint32_t regoff = (((uint32_t)rank * 4u + (uint32_t)(w >> 1)) << 9)
                    + ((uint32_t)lane << 4) + ((uint32_t)(w & 1) << 3);

    float creg[2][4][2];
    #pragma unroll
    for (int ch = 0; ch < 2; ch++)
        #pragma unroll
        for (int p = 0; p < 4; p++) { creg[ch][p][0] = 0.f; creg[ch][p][1] = 0.f; }

    for (int t = 0; t < maxT; t++) {
        uint32_t par = (uint32_t)(t & 1);

        #pragma unroll
        for (int ch = 0; ch < 2; ch++) {
            if (t >= mlen[ch]) continue;
            const uint8_t* ArF = (t & 1) ? AsF1[ch] : AsF0[ch];
            uint8_t*       AwF = (t & 1) ? AsF0[ch] : AsF1[ch];
            uint32_t       pAw = (t & 1) ? pAs0[ch] : pAs1[ch];
            const uint4*   Ar4 = (const uint4*)ArF;

            // pre-copy own 8-byte unit (frozen-row default)
            *(uint64_t*)(AwF + regoff) = *(const uint64_t*)(ArF + regoff);
            __syncwarp();

            int tk0 = toksAll[ch][gg * T + t];
            int tk1 = toksAll[ch][(gg + 8) * T + t];
            const uint32_t* xp0w = xpF + (size_t)tk0 * 512;
            const uint32_t* xp1w = xpF + (size_t)tk1 * 512;

            uint2 gq0[4], gq1[4];
            #pragma unroll
            for (int pp = 0; pp < 4; pp++) {
                int woff = ((p0 + pp) << 3) + (tg << 1);
                gq0[pp] = __ldg((const uint2*)(xp0w + woff));
                gq1[pp] = __ldg((const uint2*)(xp1w + woff));
            }

            float acc[8][4];
            #pragma unroll
            for (int nt = 0; nt < 8; nt++)
                #pragma unroll
                for (int i = 0; i < 4; i++) acc[nt][i] = 0.f;

            uint4 bb[4], bn[4];
            #pragma unroll
            for (int pp = 0; pp < 4; pp++) bb[pp] = __ldg(&Bq[(0 * 64 + p0 + pp) * 32 + lane]);
            #pragma unroll
            for (int kt = 0; kt < NKT_H; kt++) {
                if (kt < NKT_H - 1) {
                    #pragma unroll
                    for (int pp = 0; pp < 4; pp++)
                        bn[pp] = __ldg(&Bq[((kt + 1) * 64 + p0 + pp) * 32 + lane]);
                }
                uint4 av = Ar4[kt * 32 + lane];
                uint32_t a[4] = {av.x, av.y, av.z, av.w};
                #pragma unroll
                for (int pp = 0; pp < 4; pp++) {
                    mma16832(acc[2 * pp],     a, bb[pp].x, bb[pp].y);
                    mma16832(acc[2 * pp + 1], a, bb[pp].z, bb[pp].w);
                }
                #pragma unroll
                for (int pp = 0; pp < 4; pp++) bb[pp] = bn[pp];
            }

            // epilogue: active rows only
            #pragma unroll
            for (int pp = 0; pp < 4; pp++) {
                int P = p0 + pp;
                int abase = ((P >> 3) << 9) + ((gg << 2) + (P & 3)) * 16
                          + (((P >> 2) & 1) << 3) + tg;
                #pragma unroll
                for (int r = 0; r < 2; r++) {
                    int lenm = r ? len1C[ch] : len0C[ch];
                    if (t < lenm) {
                        int cb = r << 1;
                        uint32_t ew = r ? gq1[pp].x : gq0[pp].x;
                        uint32_t ow = r ? gq1[pp].y : gq0[pp].y;
                        float2 e2 = __bfloat1622float2(*(__nv_bfloat162*)&ew);
                        float2 o2 = __bfloat1622float2(*(__nv_bfloat162*)&ow);
                        float pi = acc[2 * pp][cb]     * ISCL + e2.x;
                        float pf = acc[2 * pp][cb + 1] * ISCL + e2.y;
                        float pg = acc[2 * pp + 1][cb]     * ISCL + o2.x;
                        float po = acc[2 * pp + 1][cb + 1] * ISCL + o2.y;
                        float cn = fsigm(pf) * creg[ch][pp][r] + fsigm(pi) * ftanh(pg);
                        creg[ch][pp][r] = cn;
                        float hn = fsigm(po) * ftanh(cn);
                        AwF[abase + (r << 2)] = f_to_e4m3(SCL * hn);
                        if (t == lenm - 1) {
                            int mrow = gg + (r << 3);
                            int u = (P << 2) + tg;
                            Hs[ch][mrow * 264 + u] = __float2bfloat16(hn);
                        }
                    }
                }
            }

            __syncwarp();
            {
                uint64_t v64 = *(const uint64_t*)(AwF + regoff);
                asm volatile("st.shared::cluster.u64 [%0], %1;"
                             :: "r"(pAw + regoff), "l"(v64) : "memory");
            }
            uint32_t pb = pMbar[ch], lb = ch ? mbarA1 : mbarA0;
            asm volatile("mbarrier.arrive.release.cluster.shared::cluster.b64 _, [%0];"
                         :: "r"(pb) : "memory");
            asm volatile("mbarrier.arrive.release.cluster.shared::cta.b64 _, [%0];"
                         :: "r"(lb) : "memory");
        }

        // waits after BOTH chunks' compute (each hides the other's latency)
        #pragma unroll
        for (int ch = 0; ch < 2; ch++) {
            if (t >= mlen[ch]) continue;
            uint32_t lb = ch ? mbarA1 : mbarA0;
            uint32_t done = 0;
            while (!done) {
                asm volatile(
                    "{\n\t.reg .pred p;\n\t"
                    "mbarrier.try_wait.parity.acquire.cluster.shared::cta.b64 p, [%1], %2, 0x989680;\n\t"
                    "selp.b32 %0, 1, 0, p;\n\t}"
                    : "=r"(done) : "r"(lb), "r"(par) : "memory");
            }
        }
    }

    // scatter both chunks' final h into doc accumulators
    #pragma unroll
    for (int ch = 0; ch < 2; ch++) {
        if (tid < MCH) refS[ch][tid] = refsP[ch][chunkC[ch] * MCH + tid];
    }
    __syncthreads();
    #pragma unroll
    for (int ch = 0; ch < 2; ch++) {
        float* accb = &g_acc[taskC[ch]][0][0];
        for (int idx = tid; idx < MCH * 128; idx += NT) {
            int m = idx >> 7;
            int u = (int)rank * 128 + (idx & 127);
            atomicAdd(&accb[refS[ch][m] * HID + u], __bfloat162float(Hs[ch][m * 264 + u]));
        }
    }

    asm volatile("barrier.cluster.arrive.aligned;" ::: "memory");
    asm volatile("barrier.cluster.wait.aligned;" ::: "memory");
}

// ---------------- loss ----------------
__global__ void loss_kernel(float* out) {
    int d = blockIdx.x;
    float cv = g_acc[0][d][threadIdx.x], rv = g_acc[1][d][threadIdx.x], nv = g_acc[2][d][threadIdx.x];
    float p = cv * rv, q = cv * nv;
    #pragma unroll
    for (int o = 16; o; o >>= 1) {
        p += __shfl_xor_sync(0xffffffffu, p, o);
        q += __shfl_xor_sync(0xffffffffu, q, o);
    }
    __shared__ float sp[8], sq[8];
    int w = threadIdx.x >> 5, l = threadIdx.x & 31;
    if (l == 0) { sp[w] = p; sq[w] = q; }
    __syncthreads();
    if (threadIdx.x == 0) {
        float P = 0.f, Q = 0.f;
        #pragma unroll
        for (int i = 0; i < 8; i++) { P += sp[i]; Q += sq[i]; }
        float x = P - Q;
        float lz = fmaxf(-x, 0.f) + log1pf(expf(-fabsf(x)));
        if (d == 0) lz += (float)((N_SEQ - N_DOCS) * 0.6931471805599453);
        atomicAdd(out, lz);
    }
}

// ---------------- launch ----------------
extern "C" void kernel_launch(void* const* d_in, const int* in_sizes, int n_in,
                              void* d_out, int out_size) {
    const int*   col   = (const int*)d_in[0];
    const int*   row   = (const int*)d_in[1];
    const int*   rng   = (const int*)d_in[2];
    const int*   clen  = (const int*)d_in[3];
    const int*   rlen  = (const int*)d_in[4];
    const int*   nlen  = (const int*)d_in[5];
    const int*   cref  = (const int*)d_in[6];
    const int*   rref  = (const int*)d_in[7];
    const int*   nref  = (const int*)d_in[8];
    const float* emb   = (const float*)d_in[9];
    const float* cWih  = (const float*)d_in[10];
    const float* cWhh  = (const float*)d_in[11];
    const float* cbih  = (const float*)d_in[12];
    const float* cbhh  = (const float*)d_in[13];
    const float* rWih  = (const float*)d_in[14];
    const float* rWhh  = (const float*)d_in[15];
    const float* rbih  = (const float*)d_in[16];
    const float* rbhh  = (const float*)d_in[17];
    float* out = (float*)d_out;

    prep_kernel<<<1536, 256>>>(cWih, cWhh, cbih, cbhh, rWih, rWhh, rbih, rbhh, out);
    xproj_kernel<<<2 * 1563, 256>>>(emb);
    dummy_kernel<<<1, 32>>>();
    lstm_kernel<<<768, NT>>>(col, row, rng, clen, rlen, nlen, cref, rref, nref);
    loss_kernel<<<N_DOCS, 256>>>(out);
}